// round 1
// baseline (speedup 1.0000x reference)
#include <cuda_runtime.h>

// Problem constants (fixed by the dataset)
#define TT 512
#define DD 16
#define HH 48
#define BB_TOTAL 2048

// Tiling
#define NB 16        // batch elements per CTA
#define NBI 4        // batch elements per thread
#define NGRP (NB/NBI)
#define NTHREADS (HH*NGRP)   // 192
#define NCTA (BB_TOTAL/NB)   // 128

// SMEM layout (floats)
#define W1I_OFF 0
#define W1R_OFF (W1I_OFF + DD*HH*4)
#define W2I_OFF (W1R_OFF + HH*HH*4)
#define W2R_OFF (W2I_OFF + HH*HH*4)
#define B1_OFF  (W2R_OFF + HH*HH*4)
#define B2_OFF  (B1_OFF + HH*4)
#define H1_OFF  (B2_OFF + HH*4)
#define H2_OFF  (H1_OFF + 2*NB*HH)
#define SMEM_FLOATS (H2_OFF + 2*NB*HH)
#define SMEM_BYTES  (SMEM_FLOATS * 4)

__device__ __forceinline__ float fsig(float x) {
    // sigmoid via fast exp + fast reciprocal (MUFU.EX2 + MUFU.RCP), ~1e-6 abs err
    return __fdividef(1.0f, 1.0f + __expf(-x));
}
__device__ __forceinline__ float ftanh_(float x) {
    // tanh(x) = 2*sigmoid(2x) - 1
    return __fdividef(2.0f, 1.0f + __expf(-2.0f * x)) - 1.0f;
}

__global__ void __launch_bounds__(NTHREADS, 1)
lstm2_kernel(const float* __restrict__ x,
             const float* __restrict__ Wih0, const float* __restrict__ Whh0,
             const float* __restrict__ bih0, const float* __restrict__ bhh0,
             const float* __restrict__ Wih1, const float* __restrict__ Whh1,
             const float* __restrict__ bih1, const float* __restrict__ bhh1,
             const float* __restrict__ fcw,  const float* __restrict__ fcb,
             float* __restrict__ out)
{
    extern __shared__ float sm[];
    float* W1I = sm + W1I_OFF;   // [DD][HH][4 gates]
    float* W1R = sm + W1R_OFF;   // [HH][HH][4]
    float* W2I = sm + W2I_OFF;   // [HH][HH][4]
    float* W2R = sm + W2R_OFF;   // [HH][HH][4]
    float* B1  = sm + B1_OFF;    // [HH][4]
    float* B2  = sm + B2_OFF;    // [HH][4]
    float* H1s = sm + H1_OFF;    // [2][NB][HH]
    float* H2s = sm + H2_OFF;    // [2][NB][HH]

    const int tid = threadIdx.x;

    // ---- cooperative repack of weights: W[g*HH+j][k] -> Wp[k][j][g] ----
    for (int i = tid; i < DD*HH*4; i += NTHREADS) {
        int g = i & 3, jj = (i >> 2) % HH, k = i / (HH*4);
        W1I[i] = Wih0[(g*HH + jj)*DD + k];
    }
    for (int i = tid; i < HH*HH*4; i += NTHREADS) {
        int g = i & 3, jj = (i >> 2) % HH, k = i / (HH*4);
        int r = (g*HH + jj)*HH + k;
        W1R[i] = Whh0[r];
        W2I[i] = Wih1[r];
        W2R[i] = Whh1[r];
    }
    for (int i = tid; i < HH*4; i += NTHREADS) {
        int g = i & 3, jj = i >> 2;
        B1[i] = bih0[g*HH + jj] + bhh0[g*HH + jj];
        B2[i] = bih1[g*HH + jj] + bhh1[g*HH + jj];
    }
    for (int i = tid; i < 2*NB*HH; i += NTHREADS) { H1s[i] = 0.f; H2s[i] = 0.f; }
    __syncthreads();

    const int j   = tid % HH;       // hidden index owned by this thread
    const int grp = tid / HH;       // batch group
    const int bl0 = grp * NBI;      // first local batch element
    const float* xb = x + ((long)blockIdx.x * NB + bl0) * (long)(TT*DD);

    const float4 b1 = *(const float4*)&B1[j*4];
    const float4 b2 = *(const float4*)&B2[j*4];
    float c1[NBI] = {0.f, 0.f, 0.f, 0.f};
    float c2[NBI] = {0.f, 0.f, 0.f, 0.f};

    for (int t = 0; t < TT; ++t) {
        const int cur = t & 1;
        const int nxt = cur ^ 1;

        float ai[NBI], af[NBI], ag[NBI], ao[NBI];
        #pragma unroll
        for (int bb = 0; bb < NBI; ++bb) { ai[bb]=b1.x; af[bb]=b1.y; ag[bb]=b1.z; ao[bb]=b1.w; }

        // ===== layer 1: input projection (x from global, warp-broadcast, L1-resident) =====
        #pragma unroll
        for (int k0 = 0; k0 < DD; k0 += 4) {
            float4 xv[NBI];
            #pragma unroll
            for (int bb = 0; bb < NBI; ++bb)
                xv[bb] = *(const float4*)&xb[(long)bb*(TT*DD) + t*DD + k0];
            #pragma unroll
            for (int kk = 0; kk < 4; ++kk) {
                float4 w = *(const float4*)&W1I[((k0+kk)*HH + j)*4];
                #pragma unroll
                for (int bb = 0; bb < NBI; ++bb) {
                    float xk = (kk==0)?xv[bb].x:(kk==1)?xv[bb].y:(kk==2)?xv[bb].z:xv[bb].w;
                    ai[bb] = fmaf(w.x, xk, ai[bb]);
                    af[bb] = fmaf(w.y, xk, af[bb]);
                    ag[bb] = fmaf(w.z, xk, ag[bb]);
                    ao[bb] = fmaf(w.w, xk, ao[bb]);
                }
            }
        }

        // ===== layer 1: recurrent h1 @ Whh0^T =====
        {
            const float* h1c = &H1s[cur*NB*HH + bl0*HH];
            #pragma unroll 2
            for (int k0 = 0; k0 < HH; k0 += 4) {
                float4 hv[NBI];
                #pragma unroll
                for (int bb = 0; bb < NBI; ++bb)
                    hv[bb] = *(const float4*)&h1c[bb*HH + k0];
                #pragma unroll
                for (int kk = 0; kk < 4; ++kk) {
                    float4 w = *(const float4*)&W1R[((k0+kk)*HH + j)*4];
                    #pragma unroll
                    for (int bb = 0; bb < NBI; ++bb) {
                        float hk = (kk==0)?hv[bb].x:(kk==1)?hv[bb].y:(kk==2)?hv[bb].z:hv[bb].w;
                        ai[bb] = fmaf(w.x, hk, ai[bb]);
                        af[bb] = fmaf(w.y, hk, af[bb]);
                        ag[bb] = fmaf(w.z, hk, ag[bb]);
                        ao[bb] = fmaf(w.w, hk, ao[bb]);
                    }
                }
            }
        }

        // activations -> h1[nxt]
        float* h1n = &H1s[nxt*NB*HH + bl0*HH];
        #pragma unroll
        for (int bb = 0; bb < NBI; ++bb) {
            float iv = fsig(ai[bb]);
            float fv = fsig(af[bb]);
            float gv = ftanh_(ag[bb]);
            float ov = fsig(ao[bb]);
            c1[bb] = fmaf(fv, c1[bb], iv * gv);
            h1n[bb*HH + j] = ov * ftanh_(c1[bb]);
        }
        __syncthreads();

        // ===== layer 2: gates = Wih1 @ h1_new + Whh1 @ h2_prev + b =====
        #pragma unroll
        for (int bb = 0; bb < NBI; ++bb) { ai[bb]=b2.x; af[bb]=b2.y; ag[bb]=b2.z; ao[bb]=b2.w; }
        {
            const float* h2c = &H2s[cur*NB*HH + bl0*HH];
            #pragma unroll 2
            for (int k0 = 0; k0 < HH; k0 += 4) {
                float4 uv[NBI], vv[NBI];
                #pragma unroll
                for (int bb = 0; bb < NBI; ++bb) {
                    uv[bb] = *(const float4*)&h1n[bb*HH + k0];
                    vv[bb] = *(const float4*)&h2c[bb*HH + k0];
                }
                #pragma unroll
                for (int kk = 0; kk < 4; ++kk) {
                    float4 wi = *(const float4*)&W2I[((k0+kk)*HH + j)*4];
                    float4 wr = *(const float4*)&W2R[((k0+kk)*HH + j)*4];
                    #pragma unroll
                    for (int bb = 0; bb < NBI; ++bb) {
                        float uk = (kk==0)?uv[bb].x:(kk==1)?uv[bb].y:(kk==2)?uv[bb].z:uv[bb].w;
                        float vk = (kk==0)?vv[bb].x:(kk==1)?vv[bb].y:(kk==2)?vv[bb].z:vv[bb].w;
                        ai[bb] = fmaf(wi.x, uk, ai[bb]);
                        af[bb] = fmaf(wi.y, uk, af[bb]);
                        ag[bb] = fmaf(wi.z, uk, ag[bb]);
                        ao[bb] = fmaf(wi.w, uk, ao[bb]);
                        ai[bb] = fmaf(wr.x, vk, ai[bb]);
                        af[bb] = fmaf(wr.y, vk, af[bb]);
                        ag[bb] = fmaf(wr.z, vk, ag[bb]);
                        ao[bb] = fmaf(wr.w, vk, ao[bb]);
                    }
                }
            }
        }

        float* h2n = &H2s[nxt*NB*HH + bl0*HH];
        #pragma unroll
        for (int bb = 0; bb < NBI; ++bb) {
            float iv = fsig(ai[bb]);
            float fv = fsig(af[bb]);
            float gv = ftanh_(ag[bb]);
            float ov = fsig(ao[bb]);
            c2[bb] = fmaf(fv, c2[bb], iv * gv);
            h2n[bb*HH + j] = ov * ftanh_(c2[bb]);
        }
        __syncthreads();
    }

    // ===== final FC + sigmoid. TT=512 (even): last h2 written into buffer 0 =====
    if (tid < NB) {
        const float* h2f = &H2s[0*NB*HH + tid*HH];
        float acc = fcb[0];
        #pragma unroll
        for (int jj = 0; jj < HH; ++jj)
            acc = fmaf(h2f[jj], fcw[jj], acc);
        out[blockIdx.x * NB + tid] = fsig(acc);
    }
}

extern "C" void kernel_launch(void* const* d_in, const int* in_sizes, int n_in,
                              void* d_out, int out_size) {
    (void)in_sizes; (void)n_in; (void)out_size;
    cudaFuncSetAttribute(lstm2_kernel,
                         cudaFuncAttributeMaxDynamicSharedMemorySize, SMEM_BYTES);
    lstm2_kernel<<<NCTA, NTHREADS, SMEM_BYTES>>>(
        (const float*)d_in[0],
        (const float*)d_in[1], (const float*)d_in[2],
        (const float*)d_in[3], (const float*)d_in[4],
        (const float*)d_in[5], (const float*)d_in[6],
        (const float*)d_in[7], (const float*)d_in[8],
        (const float*)d_in[9], (const float*)d_in[10],
        (float*)d_out);
}